// round 6
// baseline (speedup 1.0000x reference)
#include <cuda_runtime.h>

#define BATCH 32768
#define NIMG  5
#define DIM   512
#define DCAT  600
#define M5    (BATCH * NIMG)
#define TS    (BATCH * 200)          // per-window conv scratch stride

// Scratch (device globals — no runtime allocation allowed)
__device__ __align__(128) float g_tmp[4 * TS];       // conv window outputs
__device__ __align__(128) float g_c[BATCH * DCAT];   // conv concat [N,600]
__device__ __align__(128) float g_h[BATCH * DCAT];   // relu(fc1)   [N,600]
__device__ __align__(128) float g_ci[BATCH * DIM];   // fc2 out     [N,512]
__device__ __align__(128) float g_u[BATCH * DIM];    // ci@fc0_w[512:]+fc0_b
__device__ __align__(128) float g_score[M5];         // pre-bias scores

typedef unsigned long long ull;

// Packed dual fp32 FMA (sm_103a FFMA2). Bit-identical to two scalar FFMAs.
__device__ __forceinline__ ull fma2(ull a, ull b, ull c) {
    ull d;
    asm("fma.rn.f32x2 %0, %1, %2, %3;" : "=l"(d) : "l"(a), "l"(b), "l"(c));
    return d;
}

// ---------------------------------------------------------------------------
// Unified 128x128x8 GEMM, 8x8 per thread via f32x2 pairs (rows paired).
//   C[M,N] = op(A[M,K] @ B + bias)
//   TB=false: B is [K,N] row-major.  TB=true: B is [N,K] row-major (weights).
//   MODE 0: +bias   1: +bias,relu   2: raw store   3: fc0a score epilogue
//   grid.z: A += z*aZ (conv windows); MODE 2 also offsets C += z*cZ.
// Requires: M%128==0, K%8==0, N%4==0, lda%4==0, ldb%4==0.
// ---------------------------------------------------------------------------
template<int MODE, bool TB>
__global__ __launch_bounds__(256, 2) void gemm128(
    const float* __restrict__ A, int lda, long long aZ,
    const float* __restrict__ B, int ldb,
    const float* __restrict__ bias,
    float* __restrict__ C, int ldc, long long cZ,
    int N, int K,
    const float* __restrict__ u, const float* __restrict__ sw)
{
    __shared__ float As[2][8][132];   // [kk][row], padded
    __shared__ float Bs[2][8][264];   // [kk][2*col] duplicated pairs, padded

    const int tid  = threadIdx.x;
    const int lane = tid & 31, warp = tid >> 5;
    const int bm = blockIdx.x * 128, bn = blockIdx.y * 128;

    A += (long long)blockIdx.z * aZ;
    if (MODE == 2) C += (long long)blockIdx.z * cZ;

    // compute-fragment coordinates
    const int row0 = (warp >> 1) * 32 + (lane >> 3) * 8;   // 0..120 step 8
    const int col0 = (warp & 1) * 64 + (lane & 7) * 8;     // 0..120 step 8

    // global-load coordinates
    const int aR = tid >> 1, aK = (tid & 1) * 4;           // A (and TB-B) loader
    const int kkB = tid >> 5, colB = lane * 4;             // normal-B loader

    const float* Ag = A + (size_t)(bm + aR) * lda + aK;
    const float* Bg;
    bool bok;
    if (TB) { bok = (bn + aR) < N;   Bg = B + (size_t)(bn + aR) * ldb + aK; }
    else    { bok = (bn + colB) < N; Bg = B + (size_t)kkB * ldb + bn + colB; }

    ull acc[4][8];
#pragma unroll
    for (int i = 0; i < 4; i++)
#pragma unroll
        for (int j = 0; j < 8; j++) acc[i][j] = 0ull;

    const float4 z4 = make_float4(0.f, 0.f, 0.f, 0.f);

    // ---- prefetch tile 0 into smem[0] ----
    float4 av = *(const float4*)Ag;
    float4 bv = bok ? *(const float4*)Bg : z4;
    As[0][aK + 0][aR] = av.x; As[0][aK + 1][aR] = av.y;
    As[0][aK + 2][aR] = av.z; As[0][aK + 3][aR] = av.w;
    if (TB) {
        Bs[0][aK + 0][2 * aR] = bv.x; Bs[0][aK + 0][2 * aR + 1] = bv.x;
        Bs[0][aK + 1][2 * aR] = bv.y; Bs[0][aK + 1][2 * aR + 1] = bv.y;
        Bs[0][aK + 2][2 * aR] = bv.z; Bs[0][aK + 2][2 * aR + 1] = bv.z;
        Bs[0][aK + 3][2 * aR] = bv.w; Bs[0][aK + 3][2 * aR + 1] = bv.w;
    } else {
        *(float4*)&Bs[0][kkB][2 * colB]     = make_float4(bv.x, bv.x, bv.y, bv.y);
        *(float4*)&Bs[0][kkB][2 * colB + 4] = make_float4(bv.z, bv.z, bv.w, bv.w);
    }
    __syncthreads();

    int buf = 0;
    const int nsteps = K >> 3;
    for (int s = 0; s < nsteps; ++s) {
        const bool more = (s + 1) < nsteps;
        if (more) {                       // prefetch next tile into registers
            Ag += 8;
            av = *(const float4*)Ag;
            if (TB) { Bg += 8;                 bv = bok ? *(const float4*)Bg : z4; }
            else    { Bg += (size_t)8 * ldb;   bv = bok ? *(const float4*)Bg : z4; }
        }
        // ---- compute 8 k-slices from smem[buf] ----
#pragma unroll
        for (int kk = 0; kk < 8; kk++) {
            ulonglong2 a01 = *(const ulonglong2*)&As[buf][kk][row0];
            ulonglong2 a23 = *(const ulonglong2*)&As[buf][kk][row0 + 4];
            ull a2[4] = {a01.x, a01.y, a23.x, a23.y};
            const ulonglong2* bp = (const ulonglong2*)&Bs[buf][kk][2 * col0];
            ulonglong2 b01 = bp[0], b23 = bp[1], b45 = bp[2], b67 = bp[3];
            ull b2[8] = {b01.x, b01.y, b23.x, b23.y, b45.x, b45.y, b67.x, b67.y};
#pragma unroll
            for (int i = 0; i < 4; i++)
#pragma unroll
                for (int j = 0; j < 8; j++)
                    acc[i][j] = fma2(a2[i], b2[j], acc[i][j]);
        }
        if (more) {
            buf ^= 1;
            As[buf][aK + 0][aR] = av.x; As[buf][aK + 1][aR] = av.y;
            As[buf][aK + 2][aR] = av.z; As[buf][aK + 3][aR] = av.w;
            if (TB) {
                Bs[buf][aK + 0][2 * aR] = bv.x; Bs[buf][aK + 0][2 * aR + 1] = bv.x;
                Bs[buf][aK + 1][2 * aR] = bv.y; Bs[buf][aK + 1][2 * aR + 1] = bv.y;
                Bs[buf][aK + 2][2 * aR] = bv.z; Bs[buf][aK + 2][2 * aR + 1] = bv.z;
                Bs[buf][aK + 3][2 * aR] = bv.w; Bs[buf][aK + 3][2 * aR + 1] = bv.w;
            } else {
                *(float4*)&Bs[buf][kkB][2 * colB]     = make_float4(bv.x, bv.x, bv.y, bv.y);
                *(float4*)&Bs[buf][kkB][2 * colB + 4] = make_float4(bv.z, bv.z, bv.w, bv.w);
            }
            __syncthreads();
        }
    }

    // ---- epilogue ----
    if (MODE == 3) {
        // score partial: relu(acc + u[m/5][c]) . sw[c], reduced over this tile
        float wv[8];
#pragma unroll
        for (int j = 0; j < 8; j++) wv[j] = sw[bn + col0 + j];
#pragma unroll
        for (int i = 0; i < 4; i++) {
#pragma unroll
            for (int p = 0; p < 2; p++) {
                const int m = bm + row0 + 2 * i + p;
                const float* up = u + (size_t)(m / NIMG) * DIM + bn + col0;
                float s = 0.f;
#pragma unroll
                for (int j = 0; j < 8; j++) {
                    float2 f = *reinterpret_cast<float2*>(&acc[i][j]);
                    float v = (p == 0 ? f.x : f.y) + up[j];
                    v = fmaxf(v, 0.f);
                    s += v * wv[j];
                }
                s += __shfl_xor_sync(0xffffffffu, s, 1);
                s += __shfl_xor_sync(0xffffffffu, s, 2);
                s += __shfl_xor_sync(0xffffffffu, s, 4);
                if ((lane & 7) == 0) atomicAdd(&g_score[m], s);
            }
        }
    } else {
        float bcol[8];
        if (MODE != 2) {
#pragma unroll
            for (int j = 0; j < 8; j++) {
                int c = bn + col0 + j;
                bcol[j] = (c < N) ? bias[c] : 0.f;
            }
        }
#pragma unroll
        for (int i = 0; i < 4; i++) {
            const int r0 = bm + row0 + 2 * i;
#pragma unroll
            for (int j = 0; j < 8; j++) {
                const int c = bn + col0 + j;
                if (c < N) {
                    float2 f = *reinterpret_cast<float2*>(&acc[i][j]);
                    float v0 = f.x, v1 = f.y;
                    if (MODE != 2) { v0 += bcol[j]; v1 += bcol[j]; }
                    if (MODE == 1) { v0 = fmaxf(v0, 0.f); v1 = fmaxf(v1, 0.f); }
                    C[(size_t)r0 * ldc + c]       = v0;
                    C[(size_t)(r0 + 1) * ldc + c] = v1;
                }
            }
        }
    }
}

// Fused conv epilogue: g_c[n, coff+c] = relu(max_t g_tmp[t][n,c] + bias[c])
__global__ void conv_reduce(const float* __restrict__ bias, int T, int coff)
{
    int idx = blockIdx.x * blockDim.x + threadIdx.x;
    if (idx >= BATCH * 200) return;
    int c = idx % 200;
    int n = idx / 200;
    float v = g_tmp[idx];
    for (int t = 1; t < T; t++) v = fmaxf(v, g_tmp[(size_t)t * TS + idx]);
    g_c[(size_t)n * DCAT + coff + c] = fmaxf(v + bias[c], 0.f);
}

__global__ void zero_score()
{
    int i = blockIdx.x * blockDim.x + threadIdx.x;
    if (i < M5) g_score[i] = 0.f;
}

// FLOAT32 output: [score (M5) | rank (M5)]; rank = double-argsort of -score.
__global__ void finalize_f32(const float* __restrict__ fcs_b, float* __restrict__ out)
{
    int n = blockIdx.x * blockDim.x + threadIdx.x;
    if (n >= BATCH) return;
    float fb = fcs_b[0];
    float s[5];
#pragma unroll
    for (int i = 0; i < 5; i++) s[i] = g_score[n * 5 + i] + fb;
#pragma unroll
    for (int i = 0; i < 5; i++) {
        int si = n * 5 + i;
        out[si] = s[i];
        int r = 0;
#pragma unroll
        for (int j = 0; j < 5; j++)
            r += (s[j] > s[i]) || ((s[j] == s[i]) && (j < i));
        out[M5 + si] = (float)r;
    }
}

extern "C" void kernel_launch(void* const* d_in, const int* in_sizes, int n_in,
                              void* d_out, int out_size)
{
    const float* feats = (const float*)d_in[0];
    const float* w2    = (const float*)d_in[1];
    const float* b2    = (const float*)d_in[2];
    const float* w3    = (const float*)d_in[3];
    const float* b3    = (const float*)d_in[4];
    const float* w5    = (const float*)d_in[5];
    const float* b5    = (const float*)d_in[6];
    const float* fc1_w = (const float*)d_in[7];
    const float* fc1_b = (const float*)d_in[8];
    const float* fc2_w = (const float*)d_in[9];
    const float* fc2_b = (const float*)d_in[10];
    const float* fc0_w = (const float*)d_in[11];
    const float* fc0_b = (const float*)d_in[12];
    const float* fcs_w = (const float*)d_in[13];
    const float* fcs_b = (const float*)d_in[14];

    float *pt, *pc, *ph, *pci, *pu;
    cudaGetSymbolAddress((void**)&pt, g_tmp);
    cudaGetSymbolAddress((void**)&pc, g_c);
    cudaGetSymbolAddress((void**)&ph, g_h);
    cudaGetSymbolAddress((void**)&pci, g_ci);
    cudaGetSymbolAddress((void**)&pu, g_u);

    dim3 blk(256);
    const int MB = BATCH / 128;          // 256 M-blocks

    // conv K=2: 4 windows as grid.z GEMMs -> g_tmp, then max+bias+relu
    gemm128<2, true><<<dim3(MB, 2, 4), blk>>>(feats, NIMG * DIM, DIM,
        w2, 2 * DIM, nullptr, pt, 200, TS, 200, 2 * DIM, nullptr, nullptr);
    conv_reduce<<<(BATCH * 200 + 255) / 256, 256>>>(b2, 4, 0);

    // conv K=3: 3 windows
    gemm128<2, true><<<dim3(MB, 2, 3), blk>>>(feats, NIMG * DIM, DIM,
        w3, 3 * DIM, nullptr, pt, 200, TS, 200, 3 * DIM, nullptr, nullptr);
    conv_reduce<<<(BATCH * 200 + 255) / 256, 256>>>(b3, 3, 200);

    // conv K=5: single window -> direct bias+relu into g_c[:,400:600]
    gemm128<1, true><<<dim3(MB, 2, 1), blk>>>(feats, NIMG * DIM, 0,
        w5, 5 * DIM, b5, pc + 400, DCAT, 0, 200, 5 * DIM, nullptr, nullptr);

    // h = relu(c @ fc1_w + fc1_b)       [32768,600]x[600,600]
    gemm128<1, false><<<dim3(MB, 5, 1), blk>>>(pc, DCAT, 0,
        fc1_w, DCAT, fc1_b, ph, DCAT, 0, DCAT, DCAT, nullptr, nullptr);

    // ci = h @ fc2_w + fc2_b            [32768,600]x[600,512]
    gemm128<0, false><<<dim3(MB, 4, 1), blk>>>(ph, DCAT, 0,
        fc2_w, DIM, fc2_b, pci, DIM, 0, DIM, DCAT, nullptr, nullptr);

    // u = ci @ fc0_w[512:] + fc0_b      [32768,512]x[512,512]
    gemm128<0, false><<<dim3(MB, 4, 1), blk>>>(pci, DIM, 0,
        fc0_w + (size_t)DIM * DIM, DIM, fc0_b, pu, DIM, 0, DIM, DIM, nullptr, nullptr);

    zero_score<<<(M5 + 255) / 256, 256>>>();

    // score partials: relu(feats@fc0_w[:512] + u) . fcs_w  -> g_score
    gemm128<3, false><<<dim3(M5 / 128, 4, 1), blk>>>(feats, DIM, 0,
        fc0_w, DIM, nullptr, nullptr, 0, 0, DIM, DIM, pu, fcs_w);

    finalize_f32<<<(BATCH + 255) / 256, 256>>>(fcs_b, (float*)d_out);
}

// round 7
// speedup vs baseline: 3.1364x; 3.1364x over previous
#include <cuda_runtime.h>

#define BATCH 32768
#define NIMG  5
#define DIM   512
#define DCAT  600
#define M5    (BATCH * NIMG)
#define TS    (BATCH * 200)          // per-window conv scratch stride

// Scratch (device globals — no runtime allocation allowed)
__device__ __align__(128) float g_tmp[4 * TS];       // conv window outputs
__device__ __align__(128) float g_c[BATCH * DCAT];   // conv concat [N,600]
__device__ __align__(128) float g_h[BATCH * DCAT];   // relu(fc1)   [N,600]
__device__ __align__(128) float g_ci[BATCH * DIM];   // fc2 out     [N,512]
__device__ __align__(128) float g_u[BATCH * DIM];    // ci@fc0_w[512:]+fc0_b
__device__ __align__(128) float g_score[M5];         // pre-bias scores

// column index of fragment slot j within the warp tile (split 4+4, +32 apart)
#define COLJ(j) (((j) & 3) + (((j) >> 2) * 32))

// ---------------------------------------------------------------------------
// Unified 128x128x8 scalar-FFMA GEMM, 8x8 per thread, double-buffered smem.
//   C[M,N] = op(A[M,K] @ B + bias)
//   TB=false: B is [K,N] row-major.  TB=true: B is [N,K] row-major (weights).
//   MODE 0: +bias   1: +bias,relu   2: raw store   3: fc0a score epilogue
//   grid.z: A += z*aZ (conv windows); MODE 2 also offsets C += z*cZ.
// Requires: M%128==0, K%8==0, lda%4==0, ldb%4==0.
// ---------------------------------------------------------------------------
template<int MODE, bool TB>
__global__ __launch_bounds__(256, 2) void gemm128(
    const float* __restrict__ A, int lda, long long aZ,
    const float* __restrict__ B, int ldb,
    const float* __restrict__ bias,
    float* __restrict__ C, int ldc, long long cZ,
    int N, int K,
    const float* __restrict__ u, const float* __restrict__ sw)
{
    __shared__ float As[2][8][128];
    __shared__ float Bs[2][8][128];

    const int tid  = threadIdx.x;
    const int lane = tid & 31, warp = tid >> 5;
    const int bm = blockIdx.x * 128, bn = blockIdx.y * 128;

    A += (long long)blockIdx.z * aZ;
    if (MODE == 2) C += (long long)blockIdx.z * cZ;

    // compute-fragment coordinates
    const int row0 = (warp >> 1) * 32 + (lane >> 3) * 8;   // 8 consecutive rows
    const int col0 = (warp & 1) * 64 + (lane & 7) * 4;     // cols col0..+3, col0+32..+35

    // global-load coordinates
    const int aR = tid >> 1, aK = (tid & 1) * 4;           // A (and TB-B) loader
    const int kkB = tid >> 5, colB = lane * 4;             // normal-B loader

    const float* Ag = A + (size_t)(bm + aR) * lda + aK;
    const float* Bg;
    bool bok;
    if (TB) { bok = (bn + aR) < N;   Bg = B + (size_t)(bn + aR) * ldb + aK; }
    else    { bok = (bn + colB) < N; Bg = B + (size_t)kkB * ldb + bn + colB; }

    float acc[8][8];
#pragma unroll
    for (int i = 0; i < 8; i++)
#pragma unroll
        for (int j = 0; j < 8; j++) acc[i][j] = 0.f;

    const float4 z4 = make_float4(0.f, 0.f, 0.f, 0.f);

    // ---- prefetch tile 0 into smem[0] ----
    float4 av = *(const float4*)Ag;
    float4 bv = bok ? *(const float4*)Bg : z4;
    As[0][aK + 0][aR] = av.x; As[0][aK + 1][aR] = av.y;
    As[0][aK + 2][aR] = av.z; As[0][aK + 3][aR] = av.w;
    if (TB) {
        Bs[0][aK + 0][aR] = bv.x; Bs[0][aK + 1][aR] = bv.y;
        Bs[0][aK + 2][aR] = bv.z; Bs[0][aK + 3][aR] = bv.w;
    } else {
        *(float4*)&Bs[0][kkB][colB] = bv;
    }
    __syncthreads();

    int buf = 0;
    const int nsteps = K >> 3;
    for (int s = 0; s < nsteps; ++s) {
        const bool more = (s + 1) < nsteps;
        if (more) {                       // prefetch next tile into registers
            Ag += 8;
            av = *(const float4*)Ag;
            if (TB) { Bg += 8;               bv = bok ? *(const float4*)Bg : z4; }
            else    { Bg += (size_t)8 * ldb; bv = bok ? *(const float4*)Bg : z4; }
        }
        // ---- compute 8 k-slices from smem[buf] ----
#pragma unroll
        for (int kk = 0; kk < 8; kk++) {
            float a[8], b[8];
            *(float4*)&a[0] = *(const float4*)&As[buf][kk][row0];
            *(float4*)&a[4] = *(const float4*)&As[buf][kk][row0 + 4];
            *(float4*)&b[0] = *(const float4*)&Bs[buf][kk][col0];
            *(float4*)&b[4] = *(const float4*)&Bs[buf][kk][col0 + 32];
#pragma unroll
            for (int i = 0; i < 8; i++)
#pragma unroll
                for (int j = 0; j < 8; j++)
                    acc[i][j] += a[i] * b[j];
        }
        if (more) {
            buf ^= 1;
            As[buf][aK + 0][aR] = av.x; As[buf][aK + 1][aR] = av.y;
            As[buf][aK + 2][aR] = av.z; As[buf][aK + 3][aR] = av.w;
            if (TB) {
                Bs[buf][aK + 0][aR] = bv.x; Bs[buf][aK + 1][aR] = bv.y;
                Bs[buf][aK + 2][aR] = bv.z; Bs[buf][aK + 3][aR] = bv.w;
            } else {
                *(float4*)&Bs[buf][kkB][colB] = bv;
            }
            __syncthreads();
        }
    }

    // ---- epilogue ----
    if (MODE == 3) {
        // score partial: relu(acc + u[m/5][c]) . sw[c], reduced over this tile
        float wv[8];
#pragma unroll
        for (int j = 0; j < 8; j++) wv[j] = sw[bn + col0 + COLJ(j)];
#pragma unroll
        for (int i = 0; i < 8; i++) {
            const int m = bm + row0 + i;
            const float* up = u + (size_t)(m / NIMG) * DIM + bn + col0;
            float s = 0.f;
#pragma unroll
            for (int j = 0; j < 8; j++) {
                float v = acc[i][j] + up[COLJ(j)];
                v = fmaxf(v, 0.f);
                s += v * wv[j];
            }
            s += __shfl_xor_sync(0xffffffffu, s, 1);
            s += __shfl_xor_sync(0xffffffffu, s, 2);
            s += __shfl_xor_sync(0xffffffffu, s, 4);
            if ((lane & 7) == 0) atomicAdd(&g_score[m], s);
        }
    } else {
        float bcol[8];
        if (MODE != 2) {
#pragma unroll
            for (int j = 0; j < 8; j++) {
                int c = bn + col0 + COLJ(j);
                bcol[j] = (c < N) ? bias[c] : 0.f;
            }
        }
#pragma unroll
        for (int i = 0; i < 8; i++) {
            const int r = bm + row0 + i;
#pragma unroll
            for (int j = 0; j < 8; j++) {
                const int c = bn + col0 + COLJ(j);
                if (c < N) {
                    float v = acc[i][j];
                    if (MODE != 2) v += bcol[j];
                    if (MODE == 1) v = fmaxf(v, 0.f);
                    C[(size_t)r * ldc + c] = v;
                }
            }
        }
    }
}

// Fused conv epilogue: g_c[n, coff+c] = relu(max_t g_tmp[t][n,c] + bias[c])
__global__ void conv_reduce(const float* __restrict__ bias, int T, int coff)
{
    int idx = blockIdx.x * blockDim.x + threadIdx.x;
    if (idx >= BATCH * 200) return;
    int c = idx % 200;
    int n = idx / 200;
    float v = g_tmp[idx];
    for (int t = 1; t < T; t++) v = fmaxf(v, g_tmp[(size_t)t * TS + idx]);
    g_c[(size_t)n * DCAT + coff + c] = fmaxf(v + bias[c], 0.f);
}

__global__ void zero_score()
{
    int i = blockIdx.x * blockDim.x + threadIdx.x;
    if (i < M5) g_score[i] = 0.f;
}

// FLOAT32 output: [score (M5) | rank (M5)]; rank = double-argsort of -score.
__global__ void finalize_f32(const float* __restrict__ fcs_b, float* __restrict__ out)
{
    int n = blockIdx.x * blockDim.x + threadIdx.x;
    if (n >= BATCH) return;
    float fb = fcs_b[0];
    float s[5];
#pragma unroll
    for (int i = 0; i < 5; i++) s[i] = g_score[n * 5 + i] + fb;
#pragma unroll
    for (int i = 0; i < 5; i++) {
        int si = n * 5 + i;
        out[si] = s[i];
        int r = 0;
#pragma unroll
        for (int j = 0; j < 5; j++)
            r += (s[j] > s[i]) || ((s[j] == s[i]) && (j < i));
        out[M5 + si] = (float)r;
    }
}

extern "C" void kernel_launch(void* const* d_in, const int* in_sizes, int n_in,
                              void* d_out, int out_size)
{
    const float* feats = (const float*)d_in[0];
    const float* w2    = (const float*)d_in[1];
    const float* b2    = (const float*)d_in[2];
    const float* w3    = (const float*)d_in[3];
    const float* b3    = (const float*)d_in[4];
    const float* w5    = (const float*)d_in[5];
    const float* b5    = (const float*)d_in[6];
    const float* fc1_w = (const float*)d_in[7];
    const float* fc1_b = (const float*)d_in[8];
    const float* fc2_w = (const float*)d_in[9];
    const float* fc2_b = (const float*)d_in[10];
    const float* fc0_w = (const float*)d_in[11];
    const float* fc0_b = (const float*)d_in[12];
    const float* fcs_w = (const float*)d_in[13];
    const float* fcs_b = (const float*)d_in[14];

    float *pt, *pc, *ph, *pci, *pu;
    cudaGetSymbolAddress((void**)&pt, g_tmp);
    cudaGetSymbolAddress((void**)&pc, g_c);
    cudaGetSymbolAddress((void**)&ph, g_h);
    cudaGetSymbolAddress((void**)&pci, g_ci);
    cudaGetSymbolAddress((void**)&pu, g_u);

    dim3 blk(256);
    const int MB = BATCH / 128;          // 256 M-blocks

    // conv K=2: 4 windows as grid.z GEMMs -> g_tmp, then max+bias+relu
    gemm128<2, true><<<dim3(MB, 2, 4), blk>>>(feats, NIMG * DIM, DIM,
        w2, 2 * DIM, nullptr, pt, 200, TS, 200, 2 * DIM, nullptr, nullptr);
    conv_reduce<<<(BATCH * 200 + 255) / 256, 256>>>(b2, 4, 0);

    // conv K=3: 3 windows
    gemm128<2, true><<<dim3(MB, 2, 3), blk>>>(feats, NIMG * DIM, DIM,
        w3, 3 * DIM, nullptr, pt, 200, TS, 200, 3 * DIM, nullptr, nullptr);
    conv_reduce<<<(BATCH * 200 + 255) / 256, 256>>>(b3, 3, 200);

    // conv K=5: single window -> direct bias+relu into g_c[:,400:600]
    gemm128<1, true><<<dim3(MB, 2, 1), blk>>>(feats, NIMG * DIM, 0,
        w5, 5 * DIM, b5, pc + 400, DCAT, 0, 200, 5 * DIM, nullptr, nullptr);

    // h = relu(c @ fc1_w + fc1_b)       [32768,600]x[600,600]
    gemm128<1, false><<<dim3(MB, 5, 1), blk>>>(pc, DCAT, 0,
        fc1_w, DCAT, fc1_b, ph, DCAT, 0, DCAT, DCAT, nullptr, nullptr);

    // ci = h @ fc2_w + fc2_b            [32768,600]x[600,512]
    gemm128<0, false><<<dim3(MB, 4, 1), blk>>>(ph, DCAT, 0,
        fc2_w, DIM, fc2_b, pci, DIM, 0, DIM, DCAT, nullptr, nullptr);

    // u = ci @ fc0_w[512:] + fc0_b      [32768,512]x[512,512]
    gemm128<0, false><<<dim3(MB, 4, 1), blk>>>(pci, DIM, 0,
        fc0_w + (size_t)DIM * DIM, DIM, fc0_b, pu, DIM, 0, DIM, DIM, nullptr, nullptr);

    zero_score<<<(M5 + 255) / 256, 256>>>();

    // score partials: relu(feats@fc0_w[:512] + u) . fcs_w  -> g_score
    gemm128<3, false><<<dim3(M5 / 128, 4, 1), blk>>>(feats, DIM, 0,
        fc0_w, DIM, nullptr, nullptr, 0, 0, DIM, DIM, pu, fcs_w);

    finalize_f32<<<(BATCH + 255) / 256, 256>>>(fcs_b, (float*)d_out);
}